// round 5
// baseline (speedup 1.0000x reference)
#include <cuda_runtime.h>
#include <cuda_bf16.h>
#include <cstdint>
#include <math.h>

// Problem dims
#define B_ 32
#define L_ 64
#define E_ 512
#define U_ 512
#define V_ 32000
#define KEEPP 0.7f

// ---------------- static device scratch (no runtime allocation) ----------------
__device__ float  g_word_mask[B_*E_];          // [b][e]
__device__ float4 g_rm4[U_*B_];                // [u][b] -> 4 gate masks
__device__ float  g_fin[B_*L_*U_];             // [b*64+t][u]
__device__ float  g_x[B_*L_*E_];               // LSTM input rows = b*64+t
__device__ float  g_zin[B_*L_*4*U_];           // x@W_in + b, rows = b*64+t
__device__ float4 g_Wr4[U_*U_];                // [u][v] -> {W[u][g*512+v]}_g
__device__ float4 g_hmA[U_*B_];                // masked h ping
__device__ float4 g_hmB[U_*B_];                // masked h pong
__device__ float  g_c[U_*B_];                  // cell state [v*32+b]
__device__ float  g_rnn[B_*L_*U_];             // h*fin_mask, rows = b*64+t
__device__ int    g_is64;

// ---------------- threefry2x32, matches JAX exactly ----------------
__host__ __device__ __forceinline__ void tf2x32(uint32_t k0, uint32_t k1,
                                                uint32_t x0, uint32_t x1,
                                                uint32_t* o0, uint32_t* o1) {
  uint32_t ks2 = 0x1BD11BDAu ^ k0 ^ k1;
  uint32_t v0 = x0 + k0, v1 = x1 + k1;
#define TFR(r) { v0 += v1; v1 = (v1 << (r)) | (v1 >> (32 - (r))); v1 ^= v0; }
  TFR(13) TFR(15) TFR(26) TFR(6)  v0 += k1;  v1 += ks2 + 1u;
  TFR(17) TFR(29) TFR(16) TFR(24) v0 += ks2; v1 += k0 + 2u;
  TFR(13) TFR(15) TFR(26) TFR(6)  v0 += k0;  v1 += k1 + 3u;
  TFR(17) TFR(29) TFR(16) TFR(24) v0 += k1;  v1 += ks2 + 4u;
  TFR(13) TFR(15) TFR(26) TFR(6)  v0 += ks2; v1 += k0 + 5u;
#undef TFR
  *o0 = v0; *o1 = v1;
}

// partitionable random_bits (32-bit): bits[i] = v0^v1 of tf(key, (0, i));
// uniform = bitcast((bits>>9)|0x3f800000) - 1 ; bernoulli keep if u < 0.7
__device__ __forceinline__ float bern_val(uint32_t ka, uint32_t kb, uint32_t idx) {
  uint32_t a, b;
  tf2x32(ka, kb, 0u, idx, &a, &b);
  uint32_t bits = a ^ b;
  float u = __uint_as_float((bits >> 9) | 0x3f800000u) - 1.0f;
  return (u < KEEPP) ? (1.0f / KEEPP) : 0.0f;
}

// ---------------- small kernels ----------------
__global__ void detect_kernel(const int* __restrict__ tw) {
  // If targets are int64, hi words of first 1024 values are all 0 (values < 32000).
  // Only touches first 8KB => safe for both dtypes.
  __shared__ int s;
  if (threadIdx.x == 0) s = 0;
  __syncthreads();
  int any = 0;
  for (int i = threadIdx.x; i < 1024; i += blockDim.x) any |= tw[2*i + 1];
  if (any) atomicOr(&s, 1);
  __syncthreads();
  if (threadIdx.x == 0) g_is64 = (s == 0) ? 1 : 0;
}

__global__ void masks_kernel(uint32_t k1a, uint32_t k1b, uint32_t k2a, uint32_t k2b,
                             uint32_t k3a, uint32_t k3b) {
  uint32_t idx = blockIdx.x * blockDim.x + threadIdx.x;   // exactly 1048576 threads
  if (idx < (uint32_t)(B_*E_)) g_word_mask[idx] = bern_val(k1a, k1b, idx);
  if (idx < (uint32_t)(4*B_*U_)) {
    uint32_t g = idx >> 14, b = (idx >> 9) & 31u, u = idx & 511u;
    ((float*)g_rm4)[(u*32u + b)*4u + g] = bern_val(k2a, k2b, idx);
  }
  if (idx < (uint32_t)(U_*B_)) {
    g_hmA[idx] = make_float4(0.f, 0.f, 0.f, 0.f);
    g_c[idx] = 0.f;
  }
  g_fin[idx] = bern_val(k3a, k3b, idx);
}

__global__ void embed_kernel(const float* __restrict__ images_emb,
                             const void* __restrict__ targets,
                             const float* __restrict__ emb_table) {
  int idx = blockIdx.x * blockDim.x + threadIdx.x;        // 1048576
  int e = idx & 511, t = (idx >> 9) & 63, b = idx >> 15;
  float v;
  if (t == 0) {
    v = images_emb[b*E_ + e];
  } else {
    int w;
    if (g_is64) w = (int)((const long long*)targets)[b*L_ + (t-1)];
    else        w = ((const int*)targets)[b*L_ + (t-1)];
    v = emb_table[(size_t)w * E_ + e] * g_word_mask[b*E_ + e];
  }
  g_x[idx] = v;
}

__global__ void repack_w_kernel(const float* __restrict__ W_rec) {
  int idx = blockIdx.x * blockDim.x + threadIdx.x;        // 262144
  int v = idx & 511, u = idx >> 9;
  const float* r = W_rec + (size_t)u * 2048 + v;
  g_Wr4[u*512 + v] = make_float4(r[0], r[512], r[1024], r[1536]);
}

// ---------------- LSTM step (one launch per timestep) ----------------
__global__ __launch_bounds__(128) void lstm_step_kernel(int t, int pp) {
  const float4* __restrict__ hin  = pp ? g_hmB : g_hmA;
  float4* __restrict__       hout = pp ? g_hmA : g_hmB;
  int b  = threadIdx.x & 31;
  int vl = threadIdx.x >> 5;
  int v  = (blockIdx.x << 2) + vl;

  float ax = 0.f, ay = 0.f, az = 0.f, aw = 0.f;
  const float4* hp = hin + b;
  const float4* wp = g_Wr4 + v;
#pragma unroll 4
  for (int u = 0; u < 512; u++) {
    float4 h4 = hp[u*32];
    float4 w4 = wp[u*512];
    ax = fmaf(h4.x, w4.x, ax);
    ay = fmaf(h4.y, w4.y, ay);
    az = fmaf(h4.z, w4.z, az);
    aw = fmaf(h4.w, w4.w, aw);
  }

  int row = (b << 6) + t;
  const float* zr = g_zin + (size_t)row * 2048 + v;
  float zi = zr[0]    + ax;
  float zf = zr[512]  + ay;
  float zg = zr[1024] + az;
  float zo = zr[1536] + aw;

  float ig = 1.f / (1.f + expf(-zi));
  float fg = 1.f / (1.f + expf(-zf));
  float gv = tanhf(zg);
  float og = 1.f / (1.f + expf(-zo));

  int ci = v*32 + b;
  float cn = fmaf(fg, g_c[ci], ig * gv);
  g_c[ci] = cn;
  float hn = og * tanhf(cn);

  int ro = row*512 + v;
  g_rnn[ro] = hn * g_fin[ro];

  float4 m = g_rm4[ci];
  hout[ci] = make_float4(hn*m.x, hn*m.y, hn*m.z, hn*m.w);
}

// ---------------- tiled SGEMM with bias: C[M,N] = A[M,K]@B[K,N] + bias ----------------
// BM=BN=128, BK=16, 256 threads, 8x8 per-thread tile (4+4 split for bank-friendly LDS.128)
__global__ __launch_bounds__(256) void sgemm_bias_kernel(
    const float* __restrict__ A, const float* __restrict__ Bm,
    const float* __restrict__ bias, float* __restrict__ C,
    int M, int N, int K)
{
  __shared__ float As[16][128];
  __shared__ float Bs[16][128];

  int bm = blockIdx.y * 128;
  int bn = blockIdx.x * 128;
  int tid = threadIdx.x;
  int tx = tid & 15, ty = tid >> 4;

  float acc[8][8];
#pragma unroll
  for (int i = 0; i < 8; i++)
#pragma unroll
    for (int j = 0; j < 8; j++) acc[i][j] = 0.f;

  int arow = tid >> 2;            // 0..63
  int acol = (tid & 3) * 4;       // 0,4,8,12
  int brow = tid >> 5;            // 0..7
  int bcol = (tid & 31) * 4;      // 0..124

  for (int k0 = 0; k0 < K; k0 += 16) {
#pragma unroll
    for (int i = 0; i < 2; i++) {
      int r = arow + i*64;
      float4 va = *(const float4*)&A[(size_t)(bm + r) * K + k0 + acol];
      As[acol+0][r] = va.x; As[acol+1][r] = va.y;
      As[acol+2][r] = va.z; As[acol+3][r] = va.w;
    }
#pragma unroll
    for (int i = 0; i < 2; i++) {
      int r = brow + i*8;
      *(float4*)&Bs[r][bcol] = *(const float4*)&Bm[(size_t)(k0 + r) * N + bn + bcol];
    }
    __syncthreads();

#pragma unroll
    for (int kk = 0; kk < 16; kk++) {
      float af[8], bf[8];
      *(float4*)(af)     = *(float4*)&As[kk][ty*4];
      *(float4*)(af + 4) = *(float4*)&As[kk][ty*4 + 64];
      *(float4*)(bf)     = *(float4*)&Bs[kk][tx*4];
      *(float4*)(bf + 4) = *(float4*)&Bs[kk][tx*4 + 64];
#pragma unroll
      for (int i = 0; i < 8; i++)
#pragma unroll
        for (int j = 0; j < 8; j++)
          acc[i][j] = fmaf(af[i], bf[j], acc[i][j]);
    }
    __syncthreads();
  }

  float4 bv0 = *(const float4*)&bias[bn + tx*4];
  float4 bv1 = *(const float4*)&bias[bn + tx*4 + 64];
#pragma unroll
  for (int i = 0; i < 8; i++) {
    int row = bm + ty*4 + ((i < 4) ? i : i + 60);
    float4 o0 = make_float4(acc[i][0] + bv0.x, acc[i][1] + bv0.y,
                            acc[i][2] + bv0.z, acc[i][3] + bv0.w);
    float4 o1 = make_float4(acc[i][4] + bv1.x, acc[i][5] + bv1.y,
                            acc[i][6] + bv1.z, acc[i][7] + bv1.w);
    *(float4*)&C[(size_t)row * N + bn + tx*4]      = o0;
    *(float4*)&C[(size_t)row * N + bn + tx*4 + 64] = o1;
  }
}

// ---------------- host ----------------
extern "C" void kernel_launch(void* const* d_in, const int* in_sizes, int n_in,
                              void* d_out, int out_size) {
  (void)in_sizes; (void)n_in; (void)out_size;
  // metadata order: pos_embs(unused), images_emb, targets, emb_table, W_in, W_rec, b_lstm, W_out, b_out
  const float* images_emb = (const float*)d_in[1];
  const void*  targets    = d_in[2];
  const float* emb_table  = (const float*)d_in[3];
  const float* W_in       = (const float*)d_in[4];
  const float* W_rec      = (const float*)d_in[5];
  const float* b_lstm     = (const float*)d_in[6];
  const float* W_out      = (const float*)d_in[7];
  const float* b_out      = (const float*)d_in[8];
  float* out = (float*)d_out;

  // device addresses of scratch (symbol query, not allocation)
  void *px = nullptr, *pzin = nullptr, *prnn = nullptr;
  cudaGetSymbolAddress(&px,   g_x);
  cudaGetSymbolAddress(&pzin, g_zin);
  cudaGetSymbolAddress(&prnn, g_rnn);

  // dropout keys: mk = key(42) = (0,42); foldlike split -> k_j = threefry(mk, (0, j))
  uint32_t k1a, k1b, k2a, k2b, k3a, k3b;
  tf2x32(0u, 42u, 0u, 0u, &k1a, &k1b);
  tf2x32(0u, 42u, 0u, 1u, &k2a, &k2b);
  tf2x32(0u, 42u, 0u, 2u, &k3a, &k3b);

  detect_kernel<<<1, 128>>>((const int*)targets);
  masks_kernel<<<4096, 256>>>(k1a, k1b, k2a, k2b, k3a, k3b);
  embed_kernel<<<4096, 256>>>(images_emb, targets, emb_table);
  repack_w_kernel<<<1024, 256>>>(W_rec);

  // z_in = x @ W_in + b_lstm   [2048, 2048]
  sgemm_bias_kernel<<<dim3(16, 16), 256>>>((const float*)px, W_in, b_lstm,
                                           (float*)pzin, 2048, 2048, 512);

  // recurrence: 64 sequential step kernels (ping-pong masked-h buffers)
  for (int t = 0; t < 64; t++)
    lstm_step_kernel<<<128, 128>>>(t, t & 1);

  // predictions = rnn_out @ W_out + b_out   [2048, 32000]
  sgemm_bias_kernel<<<dim3(250, 16), 256>>>((const float*)prnn, W_out, b_out,
                                            out, 2048, 32000, 512);
}

// round 8
// speedup vs baseline: 1.1272x; 1.1272x over previous
#include <cuda_runtime.h>
#include <cuda_bf16.h>
#include <cstdint>
#include <math.h>

// Problem dims
#define B_ 32
#define L_ 64
#define E_ 512
#define U_ 512
#define V_ 32000
#define KEEPP 0.7f

// ---------------- static device scratch (no runtime allocation) ----------------
__device__ float  g_word_mask[B_*E_];          // [b][e]
__device__ float4 g_rm4[U_*B_];                // [u][b] -> 4 gate masks
__device__ float  g_fin[B_*L_*U_];             // [b*64+t][u]
__device__ float  g_x[B_*L_*E_];               // LSTM input rows = b*64+t
__device__ float  g_zin[B_*L_*4*U_];           // x@W_in + b, rows = b*64+t
__device__ float4 g_Wr4[U_*U_];                // [u][v] -> {W[u][g*512+v]}_g
__device__ float4 g_hmA[U_*B_];                // masked h ping
__device__ float4 g_hmB[U_*B_];                // masked h pong
__device__ float  g_c[U_*B_];                  // cell state [v*32+b]
__device__ float  g_rnn[B_*L_*U_];             // h*fin_mask, rows = b*64+t
__device__ int    g_is64;

// bf16 split operands for tensor-core GEMMs
__device__ __nv_bfloat16 g_Bth[(size_t)V_*512];   // W_out^T hi  [32000,512]
__device__ __nv_bfloat16 g_Btl[(size_t)V_*512];   // W_out^T lo
__device__ __nv_bfloat16 g_Wth[2048*512];         // W_in^T hi   [2048,512]
__device__ __nv_bfloat16 g_Wtl[2048*512];         // W_in^T lo
__device__ __nv_bfloat16 g_Ah[2048*512];          // A hi (g_x, later g_rnn)
__device__ __nv_bfloat16 g_Al[2048*512];          // A lo

// ---------------- threefry2x32, matches JAX exactly ----------------
__host__ __device__ __forceinline__ void tf2x32(uint32_t k0, uint32_t k1,
                                                uint32_t x0, uint32_t x1,
                                                uint32_t* o0, uint32_t* o1) {
  uint32_t ks2 = 0x1BD11BDAu ^ k0 ^ k1;
  uint32_t v0 = x0 + k0, v1 = x1 + k1;
#define TFR(r) { v0 += v1; v1 = (v1 << (r)) | (v1 >> (32 - (r))); v1 ^= v0; }
  TFR(13) TFR(15) TFR(26) TFR(6)  v0 += k1;  v1 += ks2 + 1u;
  TFR(17) TFR(29) TFR(16) TFR(24) v0 += ks2; v1 += k0 + 2u;
  TFR(13) TFR(15) TFR(26) TFR(6)  v0 += k0;  v1 += k1 + 3u;
  TFR(17) TFR(29) TFR(16) TFR(24) v0 += k1;  v1 += ks2 + 4u;
  TFR(13) TFR(15) TFR(26) TFR(6)  v0 += ks2; v1 += k0 + 5u;
#undef TFR
  *o0 = v0; *o1 = v1;
}

__device__ __forceinline__ float bern_val(uint32_t ka, uint32_t kb, uint32_t idx) {
  uint32_t a, b;
  tf2x32(ka, kb, 0u, idx, &a, &b);
  uint32_t bits = a ^ b;
  float u = __uint_as_float((bits >> 9) | 0x3f800000u) - 1.0f;
  return (u < KEEPP) ? (1.0f / KEEPP) : 0.0f;
}

// ---------------- small kernels ----------------
__global__ void detect_kernel(const int* __restrict__ tw) {
  __shared__ int s;
  if (threadIdx.x == 0) s = 0;
  __syncthreads();
  int any = 0;
  for (int i = threadIdx.x; i < 1024; i += blockDim.x) any |= tw[2*i + 1];
  if (any) atomicOr(&s, 1);
  __syncthreads();
  if (threadIdx.x == 0) g_is64 = (s == 0) ? 1 : 0;
}

__global__ void masks_kernel(uint32_t k1a, uint32_t k1b, uint32_t k2a, uint32_t k2b,
                             uint32_t k3a, uint32_t k3b) {
  uint32_t idx = blockIdx.x * blockDim.x + threadIdx.x;   // exactly 1048576 threads
  if (idx < (uint32_t)(B_*E_)) g_word_mask[idx] = bern_val(k1a, k1b, idx);
  if (idx < (uint32_t)(4*B_*U_)) {
    uint32_t g = idx >> 14, b = (idx >> 9) & 31u, u = idx & 511u;
    ((float*)g_rm4)[(u*32u + b)*4u + g] = bern_val(k2a, k2b, idx);
  }
  if (idx < (uint32_t)(U_*B_)) {
    g_hmA[idx] = make_float4(0.f, 0.f, 0.f, 0.f);
    g_c[idx] = 0.f;
  }
  g_fin[idx] = bern_val(k3a, k3b, idx);
}

__global__ void embed_kernel(const float* __restrict__ images_emb,
                             const void* __restrict__ targets,
                             const float* __restrict__ emb_table) {
  int idx = blockIdx.x * blockDim.x + threadIdx.x;        // 1048576
  int e = idx & 511, t = (idx >> 9) & 63, b = idx >> 15;
  float v;
  if (t == 0) {
    v = images_emb[b*E_ + e];
  } else {
    int w;
    if (g_is64) w = (int)((const long long*)targets)[b*L_ + (t-1)];
    else        w = ((const int*)targets)[b*L_ + (t-1)];
    v = emb_table[(size_t)w * E_ + e] * g_word_mask[b*E_ + e];
  }
  g_x[idx] = v;
}

__global__ void repack_w_kernel(const float* __restrict__ W_rec) {
  int idx = blockIdx.x * blockDim.x + threadIdx.x;        // 262144
  int v = idx & 511, u = idx >> 9;
  const float* r = W_rec + (size_t)u * 2048 + v;
  g_Wr4[u*512 + v] = make_float4(r[0], r[512], r[1024], r[1536]);
}

// transpose [512, N] fp32 -> [N, 512] bf16 hi/lo
__global__ void transpose_split_kernel(const float* __restrict__ in,
                                       __nv_bfloat16* __restrict__ oh,
                                       __nv_bfloat16* __restrict__ ol, int N) {
  __shared__ float tile[32][33];
  int tx = threadIdx.x, ty = threadIdx.y;
  int n0 = blockIdx.x * 32, k0 = blockIdx.y * 32;
#pragma unroll
  for (int j = ty; j < 32; j += 8)
    tile[j][tx] = in[(size_t)(k0 + j) * N + n0 + tx];
  __syncthreads();
#pragma unroll
  for (int j = ty; j < 32; j += 8) {
    float v = tile[tx][j];                     // in[k0+tx][n0+j]
    __nv_bfloat16 h = __float2bfloat16(v);
    size_t o = (size_t)(n0 + j) * 512 + k0 + tx;
    oh[o] = h;
    ol[o] = __float2bfloat16(v - __bfloat162float(h));
  }
}

// elementwise split [2048,512] fp32 -> bf16 hi/lo into g_Ah/g_Al
__global__ void convertA_kernel(const float* __restrict__ in) {
  int i = blockIdx.x * blockDim.x + threadIdx.x;          // 1048576
  float v = in[i];
  __nv_bfloat16 h = __float2bfloat16(v);
  g_Ah[i] = h;
  g_Al[i] = __float2bfloat16(v - __bfloat162float(h));
}

// ---------------- LSTM step (one launch per timestep) ----------------
__global__ __launch_bounds__(128) void lstm_step_kernel(int t, int pp) {
  const float4* __restrict__ hin  = pp ? g_hmB : g_hmA;
  float4* __restrict__       hout = pp ? g_hmA : g_hmB;
  int b  = threadIdx.x & 31;
  int vl = threadIdx.x >> 5;
  int v  = (blockIdx.x << 2) + vl;

  float ax = 0.f, ay = 0.f, az = 0.f, aw = 0.f;
  const float4* hp = hin + b;
  const float4* wp = g_Wr4 + v;
#pragma unroll 4
  for (int u = 0; u < 512; u++) {
    float4 h4 = hp[u*32];
    float4 w4 = wp[u*512];
    ax = fmaf(h4.x, w4.x, ax);
    ay = fmaf(h4.y, w4.y, ay);
    az = fmaf(h4.z, w4.z, az);
    aw = fmaf(h4.w, w4.w, aw);
  }

  int row = (b << 6) + t;
  const float* zr = g_zin + (size_t)row * 2048 + v;
  float zi = zr[0]    + ax;
  float zf = zr[512]  + ay;
  float zg = zr[1024] + az;
  float zo = zr[1536] + aw;

  float ig = 1.f / (1.f + expf(-zi));
  float fg = 1.f / (1.f + expf(-zf));
  float gv = tanhf(zg);
  float og = 1.f / (1.f + expf(-zo));

  int ci = v*32 + b;
  float cn = fmaf(fg, g_c[ci], ig * gv);
  g_c[ci] = cn;
  float hn = og * tanhf(cn);

  int ro = row*512 + v;
  g_rnn[ro] = hn * g_fin[ro];

  float4 m = g_rm4[ci];
  hout[ci] = make_float4(hn*m.x, hn*m.y, hn*m.z, hn*m.w);
}

// ---------------- HMMA (mma.sync) bf16x3 GEMM ----------------
// C[2048, Ntot] = (Ah+Al)[2048,512] @ (Bh+Bl)[Ntot,512]^T + bias
// CTA tile 128x128, 8 warps (2M x 4N), warp tile 64x32, BK=32, cp.async 2-stage.

__device__ __forceinline__ uint32_t smem_u32(const void* p) {
  uint32_t a;
  asm("{ .reg .u64 t; cvta.to.shared.u64 t, %1; cvt.u32.u64 %0, t; }" : "=r"(a) : "l"(p));
  return a;
}
__device__ __forceinline__ void cp16(uint32_t dst, const void* src) {
  asm volatile("cp.async.ca.shared.global [%0], [%1], 16;" :: "r"(dst), "l"(src));
}
#define LDSM4(d, a) asm volatile( \
  "ldmatrix.sync.aligned.m8n8.x4.shared.b16 {%0,%1,%2,%3}, [%4];" \
  : "=r"((d)[0]), "=r"((d)[1]), "=r"((d)[2]), "=r"((d)[3]) : "r"(a))
#define LDSM2(d, a) asm volatile( \
  "ldmatrix.sync.aligned.m8n8.x2.shared.b16 {%0,%1}, [%2];" \
  : "=r"((d)[0]), "=r"((d)[1]) : "r"(a))
#define MMA16816(ac, af, bf) asm volatile( \
  "mma.sync.aligned.m16n8k16.row.col.f32.bf16.bf16.f32 " \
  "{%0,%1,%2,%3}, {%4,%5,%6,%7}, {%8,%9}, {%0,%1,%2,%3};" \
  : "+f"((ac)[0]), "+f"((ac)[1]), "+f"((ac)[2]), "+f"((ac)[3]) \
  : "r"((af)[0]), "r"((af)[1]), "r"((af)[2]), "r"((af)[3]), \
    "r"((bf)[0]), "r"((bf)[1]))

// smem: 2 stages x {Ah, Al, Bh, Bl}; tile = 128 rows x 40 bf16 (80B stride)
#define TPB 10240
#define STG 40960
#define OFF_AH 0
#define OFF_AL TPB
#define OFF_BH (2*TPB)
#define OFF_BL (3*TPB)
#define GEMM_SMEM (2*STG)

__global__ __launch_bounds__(256) void gemm_mma_kernel(
    const __nv_bfloat16* __restrict__ Ah, const __nv_bfloat16* __restrict__ Al,
    const __nv_bfloat16* __restrict__ Bh, const __nv_bfloat16* __restrict__ Bl,
    const float* __restrict__ bias, float* __restrict__ C, int Ntot)
{
  extern __shared__ char smem[];
  uint32_t sb = smem_u32(smem);
  int tid = threadIdx.x, wid = tid >> 5, lane = tid & 31;
  int wm = wid >> 2, wn = wid & 3;
  int M0 = blockIdx.y << 7, N0 = blockIdx.x << 7;

  // loader mapping: 512 16B-chunks per tile, 2 per thread
  int r0 = tid >> 2, c0 = (tid & 3);
  uint32_t ld_d0 = (uint32_t)r0 * 80u + (uint32_t)c0 * 16u;
  uint32_t ld_d1 = (uint32_t)(r0 + 64) * 80u + (uint32_t)c0 * 16u;

  // ldmatrix per-lane base offsets
  uint32_t aBase = (uint32_t)((wm << 6) + (lane & 7) + (((lane >> 3) & 1) << 3)) * 80u
                 + (uint32_t)((lane >> 4) << 4);
  uint32_t bBase = (uint32_t)(((wn << 5) + (lane & 7))) * 80u
                 + (uint32_t)(((lane >> 3) & 1) << 4);

  float acc[4][4][4];
#pragma unroll
  for (int i = 0; i < 4; i++)
#pragma unroll
    for (int j = 0; j < 4; j++)
#pragma unroll
      for (int q = 0; q < 4; q++) acc[i][j][q] = 0.f;

  // prefetch chunk 0
  {
    uint32_t s0 = sb;
    size_t gA0 = (size_t)(M0 + r0) * 512 + c0 * 8;
    size_t gA1 = (size_t)(M0 + r0 + 64) * 512 + c0 * 8;
    size_t gB0 = (size_t)(N0 + r0) * 512 + c0 * 8;
    size_t gB1 = (size_t)(N0 + r0 + 64) * 512 + c0 * 8;
    cp16(s0 + OFF_AH + ld_d0, Ah + gA0); cp16(s0 + OFF_AH + ld_d1, Ah + gA1);
    cp16(s0 + OFF_AL + ld_d0, Al + gA0); cp16(s0 + OFF_AL + ld_d1, Al + gA1);
    cp16(s0 + OFF_BH + ld_d0, Bh + gB0); cp16(s0 + OFF_BH + ld_d1, Bh + gB1);
    cp16(s0 + OFF_BL + ld_d0, Bl + gB0); cp16(s0 + OFF_BL + ld_d1, Bl + gB1);
    asm volatile("cp.async.commit_group;" ::: "memory");
  }

  for (int kc = 0; kc < 16; kc++) {
    asm volatile("cp.async.wait_group 0;" ::: "memory");
    __syncthreads();
    if (kc + 1 < 16) {
      uint32_t s1 = sb + ((kc + 1) & 1) * STG;
      int kk = (kc + 1) * 32;
      size_t gA0 = (size_t)(M0 + r0) * 512 + kk + c0 * 8;
      size_t gA1 = (size_t)(M0 + r0 + 64) * 512 + kk + c0 * 8;
      size_t gB0 = (size_t)(N0 + r0) * 512 + kk + c0 * 8;
      size_t gB1 = (size_t)(N0 + r0 + 64) * 512 + kk + c0 * 8;
      cp16(s1 + OFF_AH + ld_d0, Ah + gA0); cp16(s1 + OFF_AH + ld_d1, Ah + gA1);
      cp16(s1 + OFF_AL + ld_d0, Al + gA0); cp16(s1 + OFF_AL + ld_d1, Al + gA1);
      cp16(s1 + OFF_BH + ld_d0, Bh + gB0); cp16(s1 + OFF_BH + ld_d1, Bh + gB1);
      cp16(s1 + OFF_BL + ld_d0, Bl + gB0); cp16(s1 + OFF_BL + ld_d1, Bl + gB1);
      asm volatile("cp.async.commit_group;" ::: "memory");
    }

    uint32_t s0 = sb + (kc & 1) * STG;
#pragma unroll
    for (int ks = 0; ks < 2; ks++) {
      uint32_t ah[4][4], al[4][4], bh[4][2], bl[4][2];
#pragma unroll
      for (int mt = 0; mt < 4; mt++) {
        uint32_t ao = aBase + (uint32_t)(mt * 1280 + ks * 32);
        LDSM4(ah[mt], s0 + OFF_AH + ao);
        LDSM4(al[mt], s0 + OFF_AL + ao);
      }
#pragma unroll
      for (int nt = 0; nt < 4; nt++) {
        uint32_t bo = bBase + (uint32_t)(nt * 640 + ks * 32);
        LDSM2(bh[nt], s0 + OFF_BH + bo);
        LDSM2(bl[nt], s0 + OFF_BL + bo);
      }
#pragma unroll
      for (int mt = 0; mt < 4; mt++)
#pragma unroll
        for (int nt = 0; nt < 4; nt++)
          MMA16816(acc[mt][nt], ah[mt], bh[nt]);
#pragma unroll
      for (int mt = 0; mt < 4; mt++)
#pragma unroll
        for (int nt = 0; nt < 4; nt++)
          MMA16816(acc[mt][nt], ah[mt], bl[nt]);
#pragma unroll
      for (int mt = 0; mt < 4; mt++)
#pragma unroll
        for (int nt = 0; nt < 4; nt++)
          MMA16816(acc[mt][nt], al[mt], bh[nt]);
    }
    __syncthreads();
  }

  // epilogue
#pragma unroll
  for (int mt = 0; mt < 4; mt++) {
    int grow = M0 + (wm << 6) + mt * 16 + (lane >> 2);
#pragma unroll
    for (int nt = 0; nt < 4; nt++) {
      int gcol = N0 + (wn << 5) + nt * 8 + (lane & 3) * 2;
      float bx = __ldg(&bias[gcol]), by = __ldg(&bias[gcol + 1]);
      float2 o0 = make_float2(acc[mt][nt][0] + bx, acc[mt][nt][1] + by);
      float2 o1 = make_float2(acc[mt][nt][2] + bx, acc[mt][nt][3] + by);
      *(float2*)&C[(size_t)grow * Ntot + gcol] = o0;
      *(float2*)&C[(size_t)(grow + 8) * Ntot + gcol] = o1;
    }
  }
}

// ---------------- host ----------------
extern "C" void kernel_launch(void* const* d_in, const int* in_sizes, int n_in,
                              void* d_out, int out_size) {
  (void)in_sizes; (void)n_in; (void)out_size;
  const float* images_emb = (const float*)d_in[1];
  const void*  targets    = d_in[2];
  const float* emb_table  = (const float*)d_in[3];
  const float* W_in       = (const float*)d_in[4];
  const float* W_rec      = (const float*)d_in[5];
  const float* b_lstm     = (const float*)d_in[6];
  const float* W_out      = (const float*)d_in[7];
  const float* b_out      = (const float*)d_in[8];
  float* out = (float*)d_out;

  void *px = nullptr, *pzin = nullptr, *prnn = nullptr;
  void *pah = nullptr, *pal = nullptr, *pbth = nullptr, *pbtl = nullptr, *pwth = nullptr, *pwtl = nullptr;
  cudaGetSymbolAddress(&px,   g_x);
  cudaGetSymbolAddress(&pzin, g_zin);
  cudaGetSymbolAddress(&prnn, g_rnn);
  cudaGetSymbolAddress(&pah,  g_Ah);
  cudaGetSymbolAddress(&pal,  g_Al);
  cudaGetSymbolAddress(&pbth, g_Bth);
  cudaGetSymbolAddress(&pbtl, g_Btl);
  cudaGetSymbolAddress(&pwth, g_Wth);
  cudaGetSymbolAddress(&pwtl, g_Wtl);

  cudaFuncSetAttribute(gemm_mma_kernel,
                       cudaFuncAttributeMaxDynamicSharedMemorySize, GEMM_SMEM);

  uint32_t k1a, k1b, k2a, k2b, k3a, k3b;
  tf2x32(0u, 42u, 0u, 0u, &k1a, &k1b);
  tf2x32(0u, 42u, 0u, 1u, &k2a, &k2b);
  tf2x32(0u, 42u, 0u, 2u, &k3a, &k3b);

  detect_kernel<<<1, 128>>>((const int*)targets);
  masks_kernel<<<4096, 256>>>(k1a, k1b, k2a, k2b, k3a, k3b);
  embed_kernel<<<4096, 256>>>(images_emb, targets, emb_table);
  repack_w_kernel<<<1024, 256>>>(W_rec);

  // weight conversions (transpose + bf16 split)
  transpose_split_kernel<<<dim3(64, 16),   dim3(32, 8)>>>(W_in,  (__nv_bfloat16*)pwth, (__nv_bfloat16*)pwtl, 2048);
  transpose_split_kernel<<<dim3(1000, 16), dim3(32, 8)>>>(W_out, (__nv_bfloat16*)pbth, (__nv_bfloat16*)pbtl, V_);

  // z_in = x @ W_in + b_lstm   [2048, 2048]
  convertA_kernel<<<4096, 256>>>((const float*)px);
  gemm_mma_kernel<<<dim3(16, 16), 256, GEMM_SMEM>>>(
      (const __nv_bfloat16*)pah, (const __nv_bfloat16*)pal,
      (const __nv_bfloat16*)pwth, (const __nv_bfloat16*)pwtl,
      b_lstm, (float*)pzin, 2048);

  // recurrence
  for (int t = 0; t < 64; t++)
    lstm_step_kernel<<<128, 128>>>(t, t & 1);

  // predictions = rnn_out @ W_out + b_out   [2048, 32000]
  convertA_kernel<<<4096, 256>>>((const float*)prnn);
  gemm_mma_kernel<<<dim3(250, 16), 256, GEMM_SMEM>>>(
      (const __nv_bfloat16*)pah, (const __nv_bfloat16*)pal,
      (const __nv_bfloat16*)pbth, (const __nv_bfloat16*)pbtl,
      b_out, out, V_);
}